// round 1
// baseline (speedup 1.0000x reference)
#include <cuda_runtime.h>
#include <cstdint>

#define N_USERS 200000
#define N_ITEMS 100000
#define N_TOTAL 300000
#define DIM     64
#define N_EDGES 4800000
#define BATCH   16384

// Scratch: three full-table buffers (76.8 MB each). Device globals — no allocation.
__device__ float g_E0 [N_TOTAL * DIM];
__device__ float g_E1 [N_TOTAL * DIM];
__device__ float g_ACC[N_TOTAL * DIM];

// ---------------------------------------------------------------------------
// k0: E0 = concat(user_embed, item_embed); ACC = E0; E1 = 0
// ---------------------------------------------------------------------------
__global__ void init_kernel(const float* __restrict__ ue,
                            const float* __restrict__ ie,
                            float* __restrict__ e0,
                            float* __restrict__ e1,
                            float* __restrict__ acc)
{
    const int total4 = N_TOTAL * DIM / 4;        // 4.8M float4
    const int user4  = N_USERS * DIM / 4;
    int i = blockIdx.x * blockDim.x + threadIdx.x;
    if (i >= total4) return;
    float4 v = (i < user4) ? reinterpret_cast<const float4*>(ue)[i]
                           : reinterpret_cast<const float4*>(ie)[i - user4];
    reinterpret_cast<float4*>(e0)[i]  = v;
    reinterpret_cast<float4*>(acc)[i] = v;
    reinterpret_cast<float4*>(e1)[i]  = make_float4(0.f, 0.f, 0.f, 0.f);
}

// ---------------------------------------------------------------------------
// scatter: for each edge e, dst_emb[ed[e]] += ev[e] * src_emb[es[e]]
// 16 threads per edge, each handling one float4 (64 floats / edge).
// Reduction via no-return vector red.global.add.v4.f32 (sm_90+).
// ---------------------------------------------------------------------------
__global__ void scatter_kernel(const float* __restrict__ src_emb,
                               float*       __restrict__ dst_emb,
                               const int*   __restrict__ es,
                               const int*   __restrict__ ed,
                               const float* __restrict__ ev)
{
    long long t = (long long)blockIdx.x * blockDim.x + threadIdx.x;
    const long long total = (long long)N_EDGES * 16;
    if (t >= total) return;
    int e = (int)(t >> 4);      // edge index
    int l = (int)(t & 15);      // float4 lane within the 64-float row

    int   s = es[e];
    int   d = ed[e];
    float v = ev[e];

    float4 x = reinterpret_cast<const float4*>(src_emb + (size_t)s * DIM)[l];
    x.x *= v; x.y *= v; x.z *= v; x.w *= v;

    float* p = dst_emb + (size_t)d * DIM + (size_t)l * 4;
    asm volatile("red.global.add.v4.f32 [%0], {%1, %2, %3, %4};"
                 :: "l"(p), "f"(x.x), "f"(x.y), "f"(x.z), "f"(x.w)
                 : "memory");
}

// ---------------------------------------------------------------------------
// accum: ACC += e_new; zero the other buffer (next scatter's target), fused.
// ---------------------------------------------------------------------------
__global__ void accum_kernel(const float* __restrict__ e_new,
                             float*       __restrict__ acc,
                             float*       __restrict__ zero_buf)
{
    const int total4 = N_TOTAL * DIM / 4;
    int i = blockIdx.x * blockDim.x + threadIdx.x;
    if (i >= total4) return;
    float4 a = reinterpret_cast<const float4*>(acc)[i];
    float4 n = reinterpret_cast<const float4*>(e_new)[i];
    a.x += n.x; a.y += n.y; a.z += n.z; a.w += n.w;
    reinterpret_cast<float4*>(acc)[i]      = a;
    reinterpret_cast<float4*>(zero_buf)[i] = make_float4(0.f, 0.f, 0.f, 0.f);
}

// ---------------------------------------------------------------------------
// gather: light_out = (ACC + E_last) / 4 ; emit users_emb, items_emb, scores.
// One warp per batch element; each lane handles a float2 (2*32 = 64).
// Output layout: [users_emb B*64][items_emb B*64][scores B]
// ---------------------------------------------------------------------------
__global__ void gather_kernel(const float* __restrict__ acc,
                              const float* __restrict__ last,
                              const int*   __restrict__ users,
                              const int*   __restrict__ items,
                              float*       __restrict__ out)
{
    int w    = (blockIdx.x * blockDim.x + threadIdx.x) >> 5;
    int lane = threadIdx.x & 31;
    if (w >= BATCH) return;

    size_t urow = (size_t)users[w] * DIM;
    size_t irow = ((size_t)items[w] + N_USERS) * DIM;

    float2 ua = reinterpret_cast<const float2*>(acc  + urow)[lane];
    float2 ul = reinterpret_cast<const float2*>(last + urow)[lane];
    float ue0 = (ua.x + ul.x) * 0.25f;
    float ue1 = (ua.y + ul.y) * 0.25f;

    float2 ia = reinterpret_cast<const float2*>(acc  + irow)[lane];
    float2 il = reinterpret_cast<const float2*>(last + irow)[lane];
    float ie0 = (ia.x + il.x) * 0.25f;
    float ie1 = (ia.y + il.y) * 0.25f;

    reinterpret_cast<float2*>(out + (size_t)w * DIM)[lane] = make_float2(ue0, ue1);
    reinterpret_cast<float2*>(out + (size_t)BATCH * DIM + (size_t)w * DIM)[lane]
        = make_float2(ie0, ie1);

    float dot = ue0 * ie0 + ue1 * ie1;
    #pragma unroll
    for (int off = 16; off > 0; off >>= 1)
        dot += __shfl_down_sync(0xFFFFFFFFu, dot, off);
    if (lane == 0)
        out[(size_t)2 * BATCH * DIM + w] = dot;
}

// ---------------------------------------------------------------------------
// Launch: inputs per metadata order:
//  0 user_embed [200000*64] f32   1 item_embed [100000*64] f32
//  2 edge_src   [4.8M] i32        3 edge_dst   [4.8M] i32
//  4 edge_val   [4.8M] f32        5 users [16384] i32   6 items [16384] i32
// ---------------------------------------------------------------------------
extern "C" void kernel_launch(void* const* d_in, const int* in_sizes, int n_in,
                              void* d_out, int out_size)
{
    const float* ue = (const float*)d_in[0];
    const float* ie = (const float*)d_in[1];
    const int*   es = (const int*)  d_in[2];
    const int*   ed = (const int*)  d_in[3];
    const float* ev = (const float*)d_in[4];
    const int*   us = (const int*)  d_in[5];
    const int*   it = (const int*)  d_in[6];
    float* out = (float*)d_out;

    float *e0, *e1, *acc;
    cudaGetSymbolAddress((void**)&e0,  g_E0);
    cudaGetSymbolAddress((void**)&e1,  g_E1);
    cudaGetSymbolAddress((void**)&acc, g_ACC);

    const int copy_blocks = (N_TOTAL * DIM / 4 + 255) / 256;          // 18750
    const long long sc_threads = (long long)N_EDGES * 16;
    const int sc_blocks = (int)((sc_threads + 255) / 256);            // 300000

    // layer pipeline (N_LAYERS = 3, unrolled)
    init_kernel<<<copy_blocks, 256>>>(ue, ie, e0, e1, acc);
    scatter_kernel<<<sc_blocks, 256>>>(e0, e1, es, ed, ev);           // emb1 -> E1
    accum_kernel  <<<copy_blocks, 256>>>(e1, acc, e0);                // ACC+=E1; E0=0
    scatter_kernel<<<sc_blocks, 256>>>(e1, e0, es, ed, ev);           // emb2 -> E0
    accum_kernel  <<<copy_blocks, 256>>>(e0, acc, e1);                // ACC+=E0; E1=0
    scatter_kernel<<<sc_blocks, 256>>>(e0, e1, es, ed, ev);           // emb3 -> E1
    gather_kernel <<<(BATCH * 32 + 255) / 256, 256>>>(acc, e1, us, it, out);
}

// round 2
// speedup vs baseline: 1.6290x; 1.6290x over previous
#include <cuda_runtime.h>
#include <cstdint>

#define N_USERS 200000
#define N_ITEMS 100000
#define N_TOTAL 300000
#define DIM     64
#define N_EDGES 4800000
#define BATCH   16384

#define SCAN_B  1024
#define NBLK    ((N_TOTAL + SCAN_B - 1) / SCAN_B)   // 293

// ---------------------------------------------------------------------------
// Device-global scratch (no allocation allowed). ~270 MB total.
// ---------------------------------------------------------------------------
__device__ float g_E1 [N_TOTAL * DIM];              // layer-1 output
__device__ float g_E2 [N_TOTAL * DIM];              // layer-2 output
__device__ float g_ACC[N_TOTAL * DIM];              // running sum of 4 terms
__device__ int   g_rowptr[N_TOTAL + 1];             // CSR row pointers (also cnt)
__device__ int   g_cursor[N_TOTAL];                 // scan tmp, then fill cursor
__device__ int   g_bsums [NBLK];                    // per-block scan sums
__device__ int2  g_edges [N_EDGES];                 // packed {src, val bits}, dst-sorted

// ---------------------------------------------------------------------------
// CSR build: zero -> histogram -> 3-step exclusive scan -> bucket scatter
// ---------------------------------------------------------------------------
__global__ void zero_cnt_kernel(int* cnt)
{
    int i = blockIdx.x * blockDim.x + threadIdx.x;
    if (i <= N_TOTAL) cnt[i] = 0;
}

__global__ void hist_kernel(const int* __restrict__ ed, int* cnt)
{
    int e = blockIdx.x * blockDim.x + threadIdx.x;
    if (e < N_EDGES) atomicAdd(&cnt[ed[e]], 1);
}

// per-block exclusive scan of cnt -> tmp, block totals -> bsums
__global__ void scan_block_kernel(const int* __restrict__ cnt, int* tmp, int* bsums)
{
    __shared__ int s[SCAN_B];
    int i = blockIdx.x * SCAN_B + threadIdx.x;
    int v = (i < N_TOTAL) ? cnt[i] : 0;
    s[threadIdx.x] = v;
    __syncthreads();
    #pragma unroll
    for (int off = 1; off < SCAN_B; off <<= 1) {
        int t = (threadIdx.x >= off) ? s[threadIdx.x - off] : 0;
        __syncthreads();
        s[threadIdx.x] += t;
        __syncthreads();
    }
    if (i < N_TOTAL) tmp[i] = s[threadIdx.x] - v;     // exclusive
    if (threadIdx.x == SCAN_B - 1) bsums[blockIdx.x] = s[SCAN_B - 1];
}

// single-block exclusive scan of the 293 block sums (512 threads)
__global__ void scan_sums_kernel(int* bsums)
{
    __shared__ int s[512];
    int tid = threadIdx.x;
    int v = (tid < NBLK) ? bsums[tid] : 0;
    s[tid] = v;
    __syncthreads();
    #pragma unroll
    for (int off = 1; off < 512; off <<= 1) {
        int t = (tid >= off) ? s[tid - off] : 0;
        __syncthreads();
        s[tid] += t;
        __syncthreads();
    }
    if (tid < NBLK) bsums[tid] = s[tid] - v;          // exclusive
}

// rowptr[i] = cursor_fill[i] = tmp[i] + bsums[i/1024]; rowptr[N] = E
__global__ void finalize_scan_kernel(const int* __restrict__ tmp,
                                     const int* __restrict__ bsums,
                                     int* rowptr, int* cursor)
{
    int i = blockIdx.x * blockDim.x + threadIdx.x;
    if (i >= N_TOTAL) return;
    int v = tmp[i] + bsums[i / SCAN_B];
    rowptr[i] = v;
    cursor[i] = v;
    if (i == 0) rowptr[N_TOTAL] = N_EDGES;
}

__global__ void csr_scatter_kernel(const int* __restrict__ es,
                                   const int* __restrict__ ed,
                                   const float* __restrict__ ev,
                                   int* cursor, int2* edges)
{
    int e = blockIdx.x * blockDim.x + threadIdx.x;
    if (e >= N_EDGES) return;
    int d   = ed[e];
    int pos = atomicAdd(&cursor[d], 1);
    edges[pos] = make_int2(es[e], __float_as_int(ev[e]));
}

// ---------------------------------------------------------------------------
// Row-wise SpMM, atomic-free. 16 threads per dst row, float4 per lane.
// MODE 1: gather from raw inputs;  emb_out = row;  ACC = base[dst] + row
// MODE 2: gather from src_emb;     emb_out = row;  ACC += row
// MODE 3: gather from src_emb;                     ACC += row   (no emb_out)
// Streaming hints (__ldcs/__stcs) on ACC/emb_out so the gather table stays
// L2-resident.
// ---------------------------------------------------------------------------
__device__ __forceinline__ const float* base_row(const float* __restrict__ ue,
                                                 const float* __restrict__ ie,
                                                 int idx)
{
    return (idx < N_USERS) ? ue + (size_t)idx * DIM
                           : ie + (size_t)(idx - N_USERS) * DIM;
}

template <int MODE>
__global__ void spmm_kernel(const float* __restrict__ ue,
                            const float* __restrict__ ie,
                            const float* __restrict__ src_emb,
                            float*       __restrict__ emb_out,
                            float*       __restrict__ acc,
                            const int*   __restrict__ rowptr,
                            const int2*  __restrict__ edges)
{
    int gid  = blockIdx.x * blockDim.x + threadIdx.x;
    int row  = gid >> 4;
    int lane = gid & 15;
    if (row >= N_TOTAL) return;

    int jb = rowptr[row];
    int je = rowptr[row + 1];

    float4 a = make_float4(0.f, 0.f, 0.f, 0.f);
    float4 b = make_float4(0.f, 0.f, 0.f, 0.f);

    int j = jb;
    for (; j + 1 < je; j += 2) {
        int2 p0 = __ldg(&edges[j]);
        int2 p1 = __ldg(&edges[j + 1]);
        const float4* r0;
        const float4* r1;
        if (MODE == 1) {
            r0 = reinterpret_cast<const float4*>(base_row(ue, ie, p0.x));
            r1 = reinterpret_cast<const float4*>(base_row(ue, ie, p1.x));
        } else {
            r0 = reinterpret_cast<const float4*>(src_emb + (size_t)p0.x * DIM);
            r1 = reinterpret_cast<const float4*>(src_emb + (size_t)p1.x * DIM);
        }
        float4 g0 = __ldg(r0 + lane);
        float4 g1 = __ldg(r1 + lane);
        float v0 = __int_as_float(p0.y);
        float v1 = __int_as_float(p1.y);
        a.x += v0 * g0.x; a.y += v0 * g0.y; a.z += v0 * g0.z; a.w += v0 * g0.w;
        b.x += v1 * g1.x; b.y += v1 * g1.y; b.z += v1 * g1.z; b.w += v1 * g1.w;
    }
    if (j < je) {
        int2 p0 = __ldg(&edges[j]);
        const float4* r0 = (MODE == 1)
            ? reinterpret_cast<const float4*>(base_row(ue, ie, p0.x))
            : reinterpret_cast<const float4*>(src_emb + (size_t)p0.x * DIM);
        float4 g0 = __ldg(r0 + lane);
        float v0 = __int_as_float(p0.y);
        a.x += v0 * g0.x; a.y += v0 * g0.y; a.z += v0 * g0.z; a.w += v0 * g0.w;
    }
    a.x += b.x; a.y += b.y; a.z += b.z; a.w += b.w;

    size_t off = (size_t)row * DIM + (size_t)lane * 4;

    if (MODE == 1) {
        float4 base = *(reinterpret_cast<const float4*>(base_row(ue, ie, row)) + lane);
        __stcs(reinterpret_cast<float4*>(emb_out + off), a);
        base.x += a.x; base.y += a.y; base.z += a.z; base.w += a.w;
        __stcs(reinterpret_cast<float4*>(acc + off), base);
    } else if (MODE == 2) {
        float4 c = __ldcs(reinterpret_cast<const float4*>(acc + off));
        __stcs(reinterpret_cast<float4*>(emb_out + off), a);
        c.x += a.x; c.y += a.y; c.z += a.z; c.w += a.w;
        __stcs(reinterpret_cast<float4*>(acc + off), c);
    } else {
        float4 c = __ldcs(reinterpret_cast<const float4*>(acc + off));
        c.x += a.x; c.y += a.y; c.z += a.z; c.w += a.w;
        __stcs(reinterpret_cast<float4*>(acc + off), c);
    }
}

// ---------------------------------------------------------------------------
// gather: light_out = ACC / 4 ; emit users_emb, items_emb, scores.
// One warp per batch element; each lane handles a float2.
// Output layout: [users_emb B*64][items_emb B*64][scores B]
// ---------------------------------------------------------------------------
__global__ void gather_kernel(const float* __restrict__ acc,
                              const int*   __restrict__ users,
                              const int*   __restrict__ items,
                              float*       __restrict__ out)
{
    int w    = (blockIdx.x * blockDim.x + threadIdx.x) >> 5;
    int lane = threadIdx.x & 31;
    if (w >= BATCH) return;

    size_t urow = (size_t)users[w] * DIM;
    size_t irow = ((size_t)items[w] + N_USERS) * DIM;

    float2 ua = reinterpret_cast<const float2*>(acc + urow)[lane];
    float ue0 = ua.x * 0.25f;
    float ue1 = ua.y * 0.25f;

    float2 ia = reinterpret_cast<const float2*>(acc + irow)[lane];
    float ie0 = ia.x * 0.25f;
    float ie1 = ia.y * 0.25f;

    reinterpret_cast<float2*>(out + (size_t)w * DIM)[lane] = make_float2(ue0, ue1);
    reinterpret_cast<float2*>(out + (size_t)BATCH * DIM + (size_t)w * DIM)[lane]
        = make_float2(ie0, ie1);

    float dot = ue0 * ie0 + ue1 * ie1;
    #pragma unroll
    for (int off = 16; off > 0; off >>= 1)
        dot += __shfl_down_sync(0xFFFFFFFFu, dot, off);
    if (lane == 0)
        out[(size_t)2 * BATCH * DIM + w] = dot;
}

// ---------------------------------------------------------------------------
// Launch. Inputs per metadata order:
//  0 user_embed f32  1 item_embed f32  2 edge_src i32  3 edge_dst i32
//  4 edge_val f32    5 users i32       6 items i32
// ---------------------------------------------------------------------------
extern "C" void kernel_launch(void* const* d_in, const int* in_sizes, int n_in,
                              void* d_out, int out_size)
{
    const float* ue = (const float*)d_in[0];
    const float* ie = (const float*)d_in[1];
    const int*   es = (const int*)  d_in[2];
    const int*   ed = (const int*)  d_in[3];
    const float* ev = (const float*)d_in[4];
    const int*   us = (const int*)  d_in[5];
    const int*   it = (const int*)  d_in[6];
    float* out = (float*)d_out;

    float *e1, *e2, *acc;
    int *rowptr, *cursor, *bsums;
    int2 *edges;
    cudaGetSymbolAddress((void**)&e1,     g_E1);
    cudaGetSymbolAddress((void**)&e2,     g_E2);
    cudaGetSymbolAddress((void**)&acc,    g_ACC);
    cudaGetSymbolAddress((void**)&rowptr, g_rowptr);
    cudaGetSymbolAddress((void**)&cursor, g_cursor);
    cudaGetSymbolAddress((void**)&bsums,  g_bsums);
    cudaGetSymbolAddress((void**)&edges,  g_edges);

    const int edge_blocks = (N_EDGES + 255) / 256;
    const int node_blocks = (N_TOTAL + 255) / 256;
    const int spmm_blocks = (N_TOTAL * 16 + 255) / 256;

    // --- CSR build (counting sort of edges by dst) ---
    zero_cnt_kernel    <<<(N_TOTAL + 256) / 256, 256>>>(rowptr);
    hist_kernel        <<<edge_blocks, 256>>>(ed, rowptr);
    scan_block_kernel  <<<NBLK, SCAN_B>>>(rowptr, cursor, bsums);
    scan_sums_kernel   <<<1, 512>>>(bsums);
    finalize_scan_kernel<<<node_blocks, 256>>>(cursor, bsums, rowptr, cursor);
    csr_scatter_kernel <<<edge_blocks, 256>>>(es, ed, ev, cursor, edges);

    // --- 3 fused SpMM layers (acc accumulated in-epilogue) ---
    spmm_kernel<1><<<spmm_blocks, 256>>>(ue, ie, nullptr, e1, acc, rowptr, edges);
    spmm_kernel<2><<<spmm_blocks, 256>>>(ue, ie, e1,      e2, acc, rowptr, edges);
    spmm_kernel<3><<<spmm_blocks, 256>>>(ue, ie, e2, nullptr, acc, rowptr, edges);

    // --- final gather + dot ---
    gather_kernel<<<(BATCH * 32 + 255) / 256, 256>>>(acc, us, it, out);
}

// round 3
// speedup vs baseline: 1.7355x; 1.0654x over previous
#include <cuda_runtime.h>
#include <cstdint>

#define N_USERS 200000
#define N_ITEMS 100000
#define N_TOTAL 300000
#define DIM     64
#define N_EDGES 4800000
#define BATCH   16384

#define SCAN_B  1024
#define NBLK    ((N_TOTAL + SCAN_B - 1) / SCAN_B)   // 293

// ---------------------------------------------------------------------------
// Device-global scratch (no allocation allowed).
// ---------------------------------------------------------------------------
__device__ float g_E1 [N_TOTAL * DIM];              // layer-1 output
__device__ float g_E2 [N_TOTAL * DIM];              // layer-2 output
__device__ float g_E3 [N_TOTAL * DIM];              // layer-3 output
__device__ int   g_rowptr[N_TOTAL + 1];             // CSR row pointers (also cnt)
__device__ int   g_cursor[N_TOTAL];                 // scan tmp, then fill cursor
__device__ int   g_bsums [NBLK];                    // per-block scan sums
__device__ int2  g_edges [N_EDGES];                 // packed {src, val bits}, dst-sorted

// ---------------------------------------------------------------------------
// CSR build: zero -> histogram -> 3-step exclusive scan -> bucket scatter
// ---------------------------------------------------------------------------
__global__ void zero_cnt_kernel(int* cnt)
{
    int i = blockIdx.x * blockDim.x + threadIdx.x;
    if (i <= N_TOTAL) cnt[i] = 0;
}

__global__ void hist_kernel(const int* __restrict__ ed, int* cnt)
{
    int e = blockIdx.x * blockDim.x + threadIdx.x;
    if (e < N_EDGES) atomicAdd(&cnt[ed[e]], 1);
}

// per-block exclusive scan of cnt -> tmp, block totals -> bsums
__global__ void scan_block_kernel(const int* __restrict__ cnt, int* tmp, int* bsums)
{
    __shared__ int s[SCAN_B];
    int i = blockIdx.x * SCAN_B + threadIdx.x;
    int v = (i < N_TOTAL) ? cnt[i] : 0;
    s[threadIdx.x] = v;
    __syncthreads();
    #pragma unroll
    for (int off = 1; off < SCAN_B; off <<= 1) {
        int t = (threadIdx.x >= off) ? s[threadIdx.x - off] : 0;
        __syncthreads();
        s[threadIdx.x] += t;
        __syncthreads();
    }
    if (i < N_TOTAL) tmp[i] = s[threadIdx.x] - v;     // exclusive
    if (threadIdx.x == SCAN_B - 1) bsums[blockIdx.x] = s[SCAN_B - 1];
}

// single-block exclusive scan of the 293 block sums (512 threads)
__global__ void scan_sums_kernel(int* bsums)
{
    __shared__ int s[512];
    int tid = threadIdx.x;
    int v = (tid < NBLK) ? bsums[tid] : 0;
    s[tid] = v;
    __syncthreads();
    #pragma unroll
    for (int off = 1; off < 512; off <<= 1) {
        int t = (tid >= off) ? s[tid - off] : 0;
        __syncthreads();
        s[tid] += t;
        __syncthreads();
    }
    if (tid < NBLK) bsums[tid] = s[tid] - v;          // exclusive
}

// rowptr[i] = cursor_fill[i] = tmp[i] + bsums[i/1024]; rowptr[N] = E
__global__ void finalize_scan_kernel(const int* __restrict__ tmp,
                                     const int* __restrict__ bsums,
                                     int* rowptr, int* cursor)
{
    int i = blockIdx.x * blockDim.x + threadIdx.x;
    if (i >= N_TOTAL) return;
    int v = tmp[i] + bsums[i / SCAN_B];
    rowptr[i] = v;
    cursor[i] = v;
    if (i == 0) rowptr[N_TOTAL] = N_EDGES;
}

__global__ void csr_scatter_kernel(const int* __restrict__ es,
                                   const int* __restrict__ ed,
                                   const float* __restrict__ ev,
                                   int* cursor, int2* edges)
{
    int e = blockIdx.x * blockDim.x + threadIdx.x;
    if (e >= N_EDGES) return;
    int d   = ed[e];
    int pos = atomicAdd(&cursor[d], 1);
    edges[pos] = make_int2(es[e], __float_as_int(ev[e]));
}

// ---------------------------------------------------------------------------
// Row-wise SpMM, atomic-free. 16 threads per dst row, float4 per lane.
// No ACC maintenance — each layer writes only its own table E_k.
// BASE_GATHER: gather from concat(ue,ie) instead of src_emb.
// STREAM_OUT : last layer's output is read only sparsely -> evict-first store.
// ---------------------------------------------------------------------------
__device__ __forceinline__ const float* base_row(const float* __restrict__ ue,
                                                 const float* __restrict__ ie,
                                                 int idx)
{
    return (idx < N_USERS) ? ue + (size_t)idx * DIM
                           : ie + (size_t)(idx - N_USERS) * DIM;
}

template <bool BASE_GATHER, bool STREAM_OUT>
__global__ void spmm_kernel(const float* __restrict__ ue,
                            const float* __restrict__ ie,
                            const float* __restrict__ src_emb,
                            float*       __restrict__ emb_out,
                            const int*   __restrict__ rowptr,
                            const int2*  __restrict__ edges)
{
    int gid  = blockIdx.x * blockDim.x + threadIdx.x;
    int row  = gid >> 4;
    int lane = gid & 15;
    if (row >= N_TOTAL) return;

    int jb = rowptr[row];
    int je = rowptr[row + 1];

    float4 a = make_float4(0.f, 0.f, 0.f, 0.f);
    float4 b = make_float4(0.f, 0.f, 0.f, 0.f);

    int j = jb;
    for (; j + 1 < je; j += 2) {
        int2 p0 = __ldg(&edges[j]);
        int2 p1 = __ldg(&edges[j + 1]);
        const float4* r0;
        const float4* r1;
        if (BASE_GATHER) {
            r0 = reinterpret_cast<const float4*>(base_row(ue, ie, p0.x));
            r1 = reinterpret_cast<const float4*>(base_row(ue, ie, p1.x));
        } else {
            r0 = reinterpret_cast<const float4*>(src_emb + (size_t)p0.x * DIM);
            r1 = reinterpret_cast<const float4*>(src_emb + (size_t)p1.x * DIM);
        }
        float4 g0 = __ldg(r0 + lane);
        float4 g1 = __ldg(r1 + lane);
        float v0 = __int_as_float(p0.y);
        float v1 = __int_as_float(p1.y);
        a.x += v0 * g0.x; a.y += v0 * g0.y; a.z += v0 * g0.z; a.w += v0 * g0.w;
        b.x += v1 * g1.x; b.y += v1 * g1.y; b.z += v1 * g1.z; b.w += v1 * g1.w;
    }
    if (j < je) {
        int2 p0 = __ldg(&edges[j]);
        const float4* r0 = BASE_GATHER
            ? reinterpret_cast<const float4*>(base_row(ue, ie, p0.x))
            : reinterpret_cast<const float4*>(src_emb + (size_t)p0.x * DIM);
        float4 g0 = __ldg(r0 + lane);
        float v0 = __int_as_float(p0.y);
        a.x += v0 * g0.x; a.y += v0 * g0.y; a.z += v0 * g0.z; a.w += v0 * g0.w;
    }
    a.x += b.x; a.y += b.y; a.z += b.z; a.w += b.w;

    size_t off = (size_t)row * DIM + (size_t)lane * 4;
    if (STREAM_OUT)
        __stcs(reinterpret_cast<float4*>(emb_out + off), a);   // evict-first
    else
        reinterpret_cast<float4*>(emb_out + off)[0] = a;       // keep in L2 for next layer
}

// ---------------------------------------------------------------------------
// gather: light_out = (base + E1 + E2 + E3) / 4 for just the batch rows;
// emit users_emb, items_emb, scores.
// One warp per batch element; each lane handles a float2.
// Output layout: [users_emb B*64][items_emb B*64][scores B]
// ---------------------------------------------------------------------------
__global__ void gather_kernel(const float* __restrict__ ue,
                              const float* __restrict__ ie,
                              const float* __restrict__ e1,
                              const float* __restrict__ e2,
                              const float* __restrict__ e3,
                              const int*   __restrict__ users,
                              const int*   __restrict__ items,
                              float*       __restrict__ out)
{
    int w    = (blockIdx.x * blockDim.x + threadIdx.x) >> 5;
    int lane = threadIdx.x & 31;
    if (w >= BATCH) return;

    int u = users[w];
    int t = items[w] + N_USERS;
    size_t urow = (size_t)u * DIM;
    size_t irow = (size_t)t * DIM;

    // user row
    float2 b0 = reinterpret_cast<const float2*>(ue + urow)[lane];
    float2 x1 = reinterpret_cast<const float2*>(e1 + urow)[lane];
    float2 x2 = reinterpret_cast<const float2*>(e2 + urow)[lane];
    float2 x3 = reinterpret_cast<const float2*>(e3 + urow)[lane];
    float ue0 = (b0.x + x1.x + x2.x + x3.x) * 0.25f;
    float ue1 = (b0.y + x1.y + x2.y + x3.y) * 0.25f;

    // item row
    float2 c0 = reinterpret_cast<const float2*>(ie + (size_t)(t - N_USERS) * DIM)[lane];
    float2 y1 = reinterpret_cast<const float2*>(e1 + irow)[lane];
    float2 y2 = reinterpret_cast<const float2*>(e2 + irow)[lane];
    float2 y3 = reinterpret_cast<const float2*>(e3 + irow)[lane];
    float ie0 = (c0.x + y1.x + y2.x + y3.x) * 0.25f;
    float ie1 = (c0.y + y1.y + y2.y + y3.y) * 0.25f;

    reinterpret_cast<float2*>(out + (size_t)w * DIM)[lane] = make_float2(ue0, ue1);
    reinterpret_cast<float2*>(out + (size_t)BATCH * DIM + (size_t)w * DIM)[lane]
        = make_float2(ie0, ie1);

    float dot = ue0 * ie0 + ue1 * ie1;
    #pragma unroll
    for (int off = 16; off > 0; off >>= 1)
        dot += __shfl_down_sync(0xFFFFFFFFu, dot, off);
    if (lane == 0)
        out[(size_t)2 * BATCH * DIM + w] = dot;
}

// ---------------------------------------------------------------------------
// Launch. Inputs per metadata order:
//  0 user_embed f32  1 item_embed f32  2 edge_src i32  3 edge_dst i32
//  4 edge_val f32    5 users i32       6 items i32
// ---------------------------------------------------------------------------
extern "C" void kernel_launch(void* const* d_in, const int* in_sizes, int n_in,
                              void* d_out, int out_size)
{
    const float* ue = (const float*)d_in[0];
    const float* ie = (const float*)d_in[1];
    const int*   es = (const int*)  d_in[2];
    const int*   ed = (const int*)  d_in[3];
    const float* ev = (const float*)d_in[4];
    const int*   us = (const int*)  d_in[5];
    const int*   it = (const int*)  d_in[6];
    float* out = (float*)d_out;

    float *e1, *e2, *e3;
    int *rowptr, *cursor, *bsums;
    int2 *edges;
    cudaGetSymbolAddress((void**)&e1,     g_E1);
    cudaGetSymbolAddress((void**)&e2,     g_E2);
    cudaGetSymbolAddress((void**)&e3,     g_E3);
    cudaGetSymbolAddress((void**)&rowptr, g_rowptr);
    cudaGetSymbolAddress((void**)&cursor, g_cursor);
    cudaGetSymbolAddress((void**)&bsums,  g_bsums);
    cudaGetSymbolAddress((void**)&edges,  g_edges);

    const int edge_blocks = (N_EDGES + 255) / 256;
    const int node_blocks = (N_TOTAL + 255) / 256;
    const int spmm_blocks = (N_TOTAL * 16 + 255) / 256;

    // --- CSR build (counting sort of edges by dst) ---
    zero_cnt_kernel    <<<(N_TOTAL + 256) / 256, 256>>>(rowptr);
    hist_kernel        <<<edge_blocks, 256>>>(ed, rowptr);
    scan_block_kernel  <<<NBLK, SCAN_B>>>(rowptr, cursor, bsums);
    scan_sums_kernel   <<<1, 512>>>(bsums);
    finalize_scan_kernel<<<node_blocks, 256>>>(cursor, bsums, rowptr, cursor);
    csr_scatter_kernel <<<edge_blocks, 256>>>(es, ed, ev, cursor, edges);

    // --- 3 SpMM layers (no ACC; each writes only its own table) ---
    spmm_kernel<true,  false><<<spmm_blocks, 256>>>(ue, ie, nullptr, e1, rowptr, edges);
    spmm_kernel<false, false><<<spmm_blocks, 256>>>(ue, ie, e1,      e2, rowptr, edges);
    spmm_kernel<false, true ><<<spmm_blocks, 256>>>(ue, ie, e2,      e3, rowptr, edges);

    // --- final sparse gather + sum + dot ---
    gather_kernel<<<(BATCH * 32 + 255) / 256, 256>>>(ue, ie, e1, e2, e3, us, it, out);
}

// round 4
// speedup vs baseline: 3.9842x; 2.2957x over previous
#include <cuda_runtime.h>
#include <cuda_fp16.h>
#include <cstdint>

#define N_USERS 200000
#define N_ITEMS 100000
#define N_TOTAL 300000
#define DIM     64
#define N_EDGES 4800000
#define BATCH   16384

#define SCAN_B  1024
#define NBLK    ((N_TOTAL + SCAN_B - 1) / SCAN_B)   // 293

// ---------------------------------------------------------------------------
// Device-global scratch (no allocation allowed).
// fp16 tables: 38.4 MB each -> L2-resident working set.
// ---------------------------------------------------------------------------
__device__ __half g_B16[N_TOTAL * DIM];             // fp16 copy of base embeddings
__device__ __half g_E1 [N_TOTAL * DIM];             // layer-1 output (fp16)
__device__ __half g_E2 [N_TOTAL * DIM];             // layer-2 output (fp16)
__device__ int    g_rowptr[N_TOTAL + 1];            // CSR row pointers (also cnt)
__device__ int    g_cursor[N_TOTAL];                // scan tmp, then fill cursor
__device__ int    g_bsums [NBLK];                   // per-block scan sums
__device__ int2   g_edges [N_EDGES];                // {src, val bits}, dst-sorted

__device__ __forceinline__ unsigned h2u(__half2 h)
{
    return *reinterpret_cast<unsigned*>(&h);
}

// ---------------------------------------------------------------------------
// base -> fp16 table
// ---------------------------------------------------------------------------
__global__ void convert_base_kernel(const float* __restrict__ ue,
                                    const float* __restrict__ ie,
                                    __half* __restrict__ b16)
{
    const int total4 = N_TOTAL * DIM / 4;
    const int user4  = N_USERS * DIM / 4;
    int i = blockIdx.x * blockDim.x + threadIdx.x;
    if (i >= total4) return;
    float4 v = (i < user4) ? __ldg(reinterpret_cast<const float4*>(ue) + i)
                           : __ldg(reinterpret_cast<const float4*>(ie) + (i - user4));
    uint2 o;
    o.x = h2u(__float22half2_rn(make_float2(v.x, v.y)));
    o.y = h2u(__float22half2_rn(make_float2(v.z, v.w)));
    reinterpret_cast<uint2*>(b16)[i] = o;
}

// ---------------------------------------------------------------------------
// CSR build: zero -> histogram -> 3-step exclusive scan -> bucket scatter
// ---------------------------------------------------------------------------
__global__ void zero_cnt_kernel(int* cnt)
{
    int i = blockIdx.x * blockDim.x + threadIdx.x;
    if (i <= N_TOTAL) cnt[i] = 0;
}

__global__ void hist_kernel(const int* __restrict__ ed, int* cnt)
{
    int e = blockIdx.x * blockDim.x + threadIdx.x;
    if (e < N_EDGES) atomicAdd(&cnt[ed[e]], 1);
}

__global__ void scan_block_kernel(const int* __restrict__ cnt, int* tmp, int* bsums)
{
    __shared__ int s[SCAN_B];
    int i = blockIdx.x * SCAN_B + threadIdx.x;
    int v = (i < N_TOTAL) ? cnt[i] : 0;
    s[threadIdx.x] = v;
    __syncthreads();
    #pragma unroll
    for (int off = 1; off < SCAN_B; off <<= 1) {
        int t = (threadIdx.x >= off) ? s[threadIdx.x - off] : 0;
        __syncthreads();
        s[threadIdx.x] += t;
        __syncthreads();
    }
    if (i < N_TOTAL) tmp[i] = s[threadIdx.x] - v;     // exclusive
    if (threadIdx.x == SCAN_B - 1) bsums[blockIdx.x] = s[SCAN_B - 1];
}

__global__ void scan_sums_kernel(int* bsums)
{
    __shared__ int s[512];
    int tid = threadIdx.x;
    int v = (tid < NBLK) ? bsums[tid] : 0;
    s[tid] = v;
    __syncthreads();
    #pragma unroll
    for (int off = 1; off < 512; off <<= 1) {
        int t = (tid >= off) ? s[tid - off] : 0;
        __syncthreads();
        s[tid] += t;
        __syncthreads();
    }
    if (tid < NBLK) bsums[tid] = s[tid] - v;          // exclusive
}

__global__ void finalize_scan_kernel(const int* __restrict__ tmp,
                                     const int* __restrict__ bsums,
                                     int* rowptr, int* cursor)
{
    int i = blockIdx.x * blockDim.x + threadIdx.x;
    if (i >= N_TOTAL) return;
    int v = tmp[i] + bsums[i / SCAN_B];
    rowptr[i] = v;
    cursor[i] = v;
    if (i == 0) rowptr[N_TOTAL] = N_EDGES;
}

__global__ void csr_scatter_kernel(const int* __restrict__ es,
                                   const int* __restrict__ ed,
                                   const float* __restrict__ ev,
                                   int* cursor, int2* edges)
{
    int e = blockIdx.x * blockDim.x + threadIdx.x;
    if (e >= N_EDGES) return;
    int d   = ed[e];
    int pos = atomicAdd(&cursor[d], 1);
    edges[pos] = make_int2(es[e], __float_as_int(ev[e]));
}

// ---------------------------------------------------------------------------
// fp16 row-wise SpMM, atomic-free. 8 lanes per dst row; each lane owns one
// 16-byte chunk (8 halfs) of the 128-byte row. One gathered row = one 128B
// line across the 8 lanes. Accumulation in fp32, output stored fp16.
// ---------------------------------------------------------------------------
__device__ __forceinline__ void fma8(float acc[8], float v, uint4 raw)
{
    float2 f0 = __half22float2(*reinterpret_cast<__half2*>(&raw.x));
    float2 f1 = __half22float2(*reinterpret_cast<__half2*>(&raw.y));
    float2 f2 = __half22float2(*reinterpret_cast<__half2*>(&raw.z));
    float2 f3 = __half22float2(*reinterpret_cast<__half2*>(&raw.w));
    acc[0] += v * f0.x; acc[1] += v * f0.y;
    acc[2] += v * f1.x; acc[3] += v * f1.y;
    acc[4] += v * f2.x; acc[5] += v * f2.y;
    acc[6] += v * f3.x; acc[7] += v * f3.y;
}

__global__ void spmm_h_kernel(const __half* __restrict__ src,
                              __half*       __restrict__ dst,
                              const int*    __restrict__ rowptr,
                              const int2*   __restrict__ edges)
{
    int gid  = blockIdx.x * blockDim.x + threadIdx.x;
    int row  = gid >> 3;
    int lane = gid & 7;
    if (row >= N_TOTAL) return;

    int jb = rowptr[row];
    int je = rowptr[row + 1];

    float acc[8] = {0.f, 0.f, 0.f, 0.f, 0.f, 0.f, 0.f, 0.f};

    int j = jb;
    for (; j + 1 < je; j += 2) {
        int2 p0 = __ldg(&edges[j]);
        int2 p1 = __ldg(&edges[j + 1]);
        uint4 r0 = __ldg(reinterpret_cast<const uint4*>(src + (size_t)p0.x * DIM) + lane);
        uint4 r1 = __ldg(reinterpret_cast<const uint4*>(src + (size_t)p1.x * DIM) + lane);
        fma8(acc, __int_as_float(p0.y), r0);
        fma8(acc, __int_as_float(p1.y), r1);
    }
    if (j < je) {
        int2 p0 = __ldg(&edges[j]);
        uint4 r0 = __ldg(reinterpret_cast<const uint4*>(src + (size_t)p0.x * DIM) + lane);
        fma8(acc, __int_as_float(p0.y), r0);
    }

    uint4 o;
    o.x = h2u(__float22half2_rn(make_float2(acc[0], acc[1])));
    o.y = h2u(__float22half2_rn(make_float2(acc[2], acc[3])));
    o.z = h2u(__float22half2_rn(make_float2(acc[4], acc[5])));
    o.w = h2u(__float22half2_rn(make_float2(acc[6], acc[7])));
    reinterpret_cast<uint4*>(dst + (size_t)row * DIM)[lane] = o;
}

// ---------------------------------------------------------------------------
// Fused layer-3 + final gather. One warp per batch entry; each lane owns a
// half2 column pair. For both the user row and the item row:
//   e3 = sum over edges(row) of val * E2[src]   (computed on the fly)
//   light = (base_fp32 + E1 + E2 + e3) / 4
// Output layout: [users_emb B*64][items_emb B*64][scores B]
// ---------------------------------------------------------------------------
__device__ __forceinline__ float2 final_row(int row,
                                            const float*  __restrict__ base_row_ptr,
                                            const __half* __restrict__ e1,
                                            const __half* __restrict__ e2,
                                            const int*    __restrict__ rowptr,
                                            const int2*   __restrict__ edges,
                                            int lane)
{
    float ax = 0.f, ay = 0.f;
    int jb = rowptr[row];
    int je = rowptr[row + 1];
    for (int j = jb; j < je; ++j) {
        int2 p = __ldg(&edges[j]);
        float v = __int_as_float(p.y);
        __half2 h = __ldg(reinterpret_cast<const __half2*>(e2 + (size_t)p.x * DIM) + lane);
        float2 f = __half22float2(h);
        ax += v * f.x;
        ay += v * f.y;
    }
    float2 b  = reinterpret_cast<const float2*>(base_row_ptr)[lane];
    float2 f1 = __half22float2(
        __ldg(reinterpret_cast<const __half2*>(e1 + (size_t)row * DIM) + lane));
    float2 f2 = __half22float2(
        __ldg(reinterpret_cast<const __half2*>(e2 + (size_t)row * DIM) + lane));
    return make_float2((b.x + f1.x + f2.x + ax) * 0.25f,
                       (b.y + f1.y + f2.y + ay) * 0.25f);
}

__global__ void gather3_kernel(const float*  __restrict__ ue,
                               const float*  __restrict__ ie,
                               const __half* __restrict__ e1,
                               const __half* __restrict__ e2,
                               const int*    __restrict__ rowptr,
                               const int2*   __restrict__ edges,
                               const int*    __restrict__ users,
                               const int*    __restrict__ items,
                               float*        __restrict__ out)
{
    int w    = (blockIdx.x * blockDim.x + threadIdx.x) >> 5;
    int lane = threadIdx.x & 31;
    if (w >= BATCH) return;

    int u = users[w];
    int t = items[w] + N_USERS;

    float2 uemb = final_row(u, ue + (size_t)u * DIM, e1, e2, rowptr, edges, lane);
    float2 iemb = final_row(t, ie + (size_t)(t - N_USERS) * DIM, e1, e2, rowptr, edges, lane);

    reinterpret_cast<float2*>(out + (size_t)w * DIM)[lane] = uemb;
    reinterpret_cast<float2*>(out + (size_t)BATCH * DIM + (size_t)w * DIM)[lane] = iemb;

    float dot = uemb.x * iemb.x + uemb.y * iemb.y;
    #pragma unroll
    for (int off = 16; off > 0; off >>= 1)
        dot += __shfl_down_sync(0xFFFFFFFFu, dot, off);
    if (lane == 0)
        out[(size_t)2 * BATCH * DIM + w] = dot;
}

// ---------------------------------------------------------------------------
// Launch. Inputs per metadata order:
//  0 user_embed f32  1 item_embed f32  2 edge_src i32  3 edge_dst i32
//  4 edge_val f32    5 users i32       6 items i32
// ---------------------------------------------------------------------------
extern "C" void kernel_launch(void* const* d_in, const int* in_sizes, int n_in,
                              void* d_out, int out_size)
{
    const float* ue = (const float*)d_in[0];
    const float* ie = (const float*)d_in[1];
    const int*   es = (const int*)  d_in[2];
    const int*   ed = (const int*)  d_in[3];
    const float* ev = (const float*)d_in[4];
    const int*   us = (const int*)  d_in[5];
    const int*   it = (const int*)  d_in[6];
    float* out = (float*)d_out;

    __half *b16, *e1, *e2;
    int *rowptr, *cursor, *bsums;
    int2 *edges;
    cudaGetSymbolAddress((void**)&b16,    g_B16);
    cudaGetSymbolAddress((void**)&e1,     g_E1);
    cudaGetSymbolAddress((void**)&e2,     g_E2);
    cudaGetSymbolAddress((void**)&rowptr, g_rowptr);
    cudaGetSymbolAddress((void**)&cursor, g_cursor);
    cudaGetSymbolAddress((void**)&bsums,  g_bsums);
    cudaGetSymbolAddress((void**)&edges,  g_edges);

    const int edge_blocks = (N_EDGES + 255) / 256;
    const int node_blocks = (N_TOTAL + 255) / 256;
    const int conv_blocks = (N_TOTAL * DIM / 4 + 255) / 256;
    const int spmm_blocks = (N_TOTAL * 8 + 255) / 256;

    // --- base -> fp16 table ---
    convert_base_kernel<<<conv_blocks, 256>>>(ue, ie, b16);

    // --- CSR build (counting sort of edges by dst) ---
    zero_cnt_kernel     <<<(N_TOTAL + 256) / 256, 256>>>(rowptr);
    hist_kernel         <<<edge_blocks, 256>>>(ed, rowptr);
    scan_block_kernel   <<<NBLK, SCAN_B>>>(rowptr, cursor, bsums);
    scan_sums_kernel    <<<1, 512>>>(bsums);
    finalize_scan_kernel<<<node_blocks, 256>>>(cursor, bsums, rowptr, cursor);
    csr_scatter_kernel  <<<edge_blocks, 256>>>(es, ed, ev, cursor, edges);

    // --- 2 fp16 SpMM layers ---
    spmm_h_kernel<<<spmm_blocks, 256>>>(b16, e1, rowptr, edges);
    spmm_h_kernel<<<spmm_blocks, 256>>>(e1,  e2, rowptr, edges);

    // --- fused layer-3 + gather + dot ---
    gather3_kernel<<<(BATCH * 32 + 255) / 256, 256>>>(ue, ie, e1, e2, rowptr, edges,
                                                      us, it, out);
}